// round 10
// baseline (speedup 1.0000x reference)
#include <cuda_runtime.h>
#include <cuda_bf16.h>
#include <cstdint>

#define NN 8192
#define FIN 512
#define FOUT 64

// ---------------- scratch globals (no allocations allowed) ----------------
__device__ float g_h[NN * FOUT];
__device__ float g_ssrc[NN];
__device__ float g_G[NN];                    // exp(0.8 * s_src)
__device__ float4 g_colf[NN];                // {F=exp(sd), F02=exp(0.2 sd), sd, 0}
__device__ __nv_bfloat16 g_HThi[FOUT * NN];  // H^T high bf16, [f][i]
__device__ __nv_bfloat16 g_HTlo[FOUT * NN];  // H^T residual bf16
__device__ float g_part[2 * NN * FOUT];      // partial numerators per j-half
__device__ float g_psum[2 * NN];             // partial row sums per j-half

__device__ __forceinline__ uint32_t smem_u32(const void* p) {
    uint32_t a;
    asm("{ .reg .u64 t; cvta.to.shared.u64 t, %1; cvt.u32.u64 %0, t; }" : "=r"(a) : "l"(p));
    return a;
}
__device__ __forceinline__ void ldsm4(uint32_t* r, uint32_t addr) {
    asm volatile("ldmatrix.sync.aligned.m8n8.x4.shared.b16 {%0,%1,%2,%3}, [%4];"
                 : "=r"(r[0]), "=r"(r[1]), "=r"(r[2]), "=r"(r[3]) : "r"(addr));
}
__device__ __forceinline__ void mma_bf16(float* c, const uint32_t* a, uint32_t b0, uint32_t b1) {
    asm volatile(
        "mma.sync.aligned.m16n8k16.row.col.f32.bf16.bf16.f32 "
        "{%0,%1,%2,%3}, {%4,%5,%6,%7}, {%8,%9}, {%0,%1,%2,%3};"
        : "+f"(c[0]), "+f"(c[1]), "+f"(c[2]), "+f"(c[3])
        : "r"(a[0]), "r"(a[1]), "r"(a[2]), "r"(a[3]), "r"(b0), "r"(b1));
}
__device__ __forceinline__ void cpasync16(uint32_t dst, const void* src) {
    asm volatile("cp.async.cg.shared.global [%0], [%1], 16;" :: "r"(dst), "l"(src));
}
__device__ __forceinline__ void cp_commit() { asm volatile("cp.async.commit_group;"); }
__device__ __forceinline__ void cp_wait0() { asm volatile("cp.async.wait_group 0;" ::: "memory"); }

// ---------------- Kernel A: h = X @ W ----------------
__global__ __launch_bounds__(256) void k_gemm_h(const float* __restrict__ X,
                                                const float* __restrict__ W,
                                                float* __restrict__ H) {
    __shared__ float sA[32][65];
    __shared__ float sB[32][68];
    int t = threadIdx.x;
    int m0 = blockIdx.x * 64;
    int tr = t >> 4, tc = t & 15;
    float acc[4][4];
#pragma unroll
    for (int i = 0; i < 4; i++)
#pragma unroll
        for (int j = 0; j < 4; j++) acc[i][j] = 0.f;

    float rA[8], rB[8];
#pragma unroll
    for (int u = 0; u < 8; u++) {
        int g = u * 256 + t;
        int m = g >> 5, k = g & 31;
        rA[u] = X[(m0 + m) * FIN + k];
    }
#pragma unroll
    for (int u = 0; u < 8; u++) {
        int g = u * 256 + t;
        int k = g >> 6, n = g & 63;
        rB[u] = W[k * FOUT + n];
    }

    for (int kc = 0; kc < 16; kc++) {
        __syncthreads();
#pragma unroll
        for (int u = 0; u < 8; u++) {
            int g = u * 256 + t;
            int m = g >> 5, k = g & 31;
            sA[k][m] = rA[u];
        }
#pragma unroll
        for (int u = 0; u < 8; u++) {
            int g = u * 256 + t;
            int k = g >> 6, n = g & 63;
            sB[k][n] = rB[u];
        }
        __syncthreads();
        if (kc + 1 < 16) {
            int k0 = (kc + 1) * 32;
#pragma unroll
            for (int u = 0; u < 8; u++) {
                int g = u * 256 + t;
                int m = g >> 5, k = g & 31;
                rA[u] = X[(m0 + m) * FIN + k0 + k];
            }
#pragma unroll
            for (int u = 0; u < 8; u++) {
                int g = u * 256 + t;
                int k = g >> 6, n = g & 63;
                rB[u] = W[(k0 + k) * FOUT + n];
            }
        }
#pragma unroll
        for (int k = 0; k < 32; k++) {
            float a[4], b[4];
#pragma unroll
            for (int i = 0; i < 4; i++) a[i] = sA[k][tr + 16 * i];
#pragma unroll
            for (int j = 0; j < 4; j++) b[j] = sB[k][tc + 16 * j];
#pragma unroll
            for (int i = 0; i < 4; i++)
#pragma unroll
                for (int j = 0; j < 4; j++) acc[i][j] += a[i] * b[j];
        }
    }
#pragma unroll
    for (int i = 0; i < 4; i++)
#pragma unroll
        for (int j = 0; j < 4; j++)
            H[(m0 + tr + 16 * i) * FOUT + tc + 16 * j] = acc[i][j];
}

// ---------------- Kernel A2: scores + exp factors ----------------
__global__ __launch_bounds__(256) void k_scores(const float* __restrict__ H,
                                                const float* __restrict__ a) {
    int i = blockIdx.x * blockDim.x + threadIdx.x;
    const float4* hr = (const float4*)(H + i * FOUT);
    const float4* av = (const float4*)a;
    float ss = 0.f, sd = 0.f;
#pragma unroll
    for (int f = 0; f < 16; f++) {
        float4 h = hr[f];
        float4 as = av[f];
        float4 ad = av[16 + f];
        ss += h.x * as.x + h.y * as.y + h.z * as.z + h.w * as.w;
        sd += h.x * ad.x + h.y * ad.y + h.z * ad.z + h.w * ad.w;
    }
    g_ssrc[i] = ss;
    g_G[i] = expf(0.8f * ss);
    g_colf[i] = make_float4(expf(sd), expf(0.2f * sd), sd, 0.f);
}

// ---------------- Kernel A3: transpose H -> HT hi/lo bf16 ----------------
__global__ __launch_bounds__(256) void k_transpose() {
    __shared__ float tile[64][65];
    int t = threadIdx.x;
    int i0 = blockIdx.x * 64;
#pragma unroll
    for (int u = 0; u < 16; u++) {
        int idx = u * 256 + t;
        int r = idx >> 6, c = idx & 63;
        tile[r][c] = g_h[(i0 + r) * FOUT + c];
    }
    __syncthreads();
#pragma unroll
    for (int u = 0; u < 16; u++) {
        int idx = u * 256 + t;
        int f = idx >> 6, i = idx & 63;
        float v = tile[i][f];
        __nv_bfloat16 hb = __float2bfloat16(v);
        float hv = __bfloat162float(hb);
        __nv_bfloat16 lb = __float2bfloat16(v - hv);
        g_HThi[f * NN + i0 + i] = hb;
        g_HTlo[f * NN + i0 + i] = lb;
    }
}

// ---------------- Kernel B: HMMA attention, cp.async pipelined ----------------
// smem (u32):
//   sPhi   [128][68]              at 0       (8704)
//   sPlo   [128][68]              at 8704    (8704)
//   sB     2 x {hi 4352, lo 4352} at 17408   (17408)
//   sAdj   [128][132]             at 34816   (16896)
#define SPS 68
#define SAS 132
#define SB_OFF 17408
#define SADJ_OFF 34816
#define SMEM_U32 51712  // 206848 bytes

__global__ __launch_bounds__(256, 1) void k_attn(const int* __restrict__ adj) {
    extern __shared__ uint32_t sm[];
    uint32_t* sPhi = sm;
    uint32_t* sPlo = sm + 8704;
    uint32_t* sAdj = sm + SADJ_OFF;
    uint32_t smbase = smem_u32(sm);

    int t = threadIdx.x;
    int w = t >> 5, lane = t & 31;
    int g = lane >> 2, tg = lane & 3;
    int rb = (int)blockIdx.x >> 1, jh = (int)blockIdx.x & 1;
    int i0 = rb * 128, jbase = jh * 4096;

    // ---- P-build mapping: thread -> (row, half of 64 cols) ----
    int row = t >> 1;
    int half = t & 1;
    float si = g_ssrc[i0 + row];
    float Gi = g_G[i0 + row];
    float nsi = -si;
    float rsum = 0.f;
    uint64_t* pDhi = (uint64_t*)sPhi + (size_t)row * (SPS / 2) + half * 16;
    uint64_t* pDlo = (uint64_t*)sPlo + (size_t)row * (SPS / 2) + half * 16;
    const int4* adjS = (const int4*)(sAdj + row * SAS + half * 64);

    // cp.async source/dest mappings (per thread)
    int a_row = t >> 1, a_c4 = (t & 1) * 16;           // adj: 2 threads/row, 16 chunks each? no:
    // adj: 4096 chunks (128 rows x 32); thread covers idx = u*256+t
    // B: hi/lo 1024 chunks each (64 rows x 16)

    // ---- MMA mapping: 8 warps = 4(wr) x 2(wc), warp tile 32m x 32n ----
    int wr = w >> 1, wc = w & 1;
    int a_r = ((lane >> 3) & 1) * 8 + (lane & 7);
    uint32_t a_cb = (uint32_t)(lane >> 4) * 16u;
    int b_r = (lane >> 4) * 8 + (lane & 7);
    uint32_t b_cb = (uint32_t)((lane >> 3) & 1) * 16u;

    uint32_t aPhi = smbase + (uint32_t)((wr * 32 + a_r) * SPS) * 4u + a_cb;
    uint32_t aPlo = aPhi + 8704u * 4u;
    uint32_t bB_l = smbase + SB_OFF * 4u + (uint32_t)((wc * 32 + b_r) * SPS) * 4u + b_cb;
    const uint32_t mstep = 16u * SPS * 4u;
    const uint32_t nstep = 16u * SPS * 4u;

    float acc[2][4][4];
#pragma unroll
    for (int mi = 0; mi < 2; mi++)
#pragma unroll
        for (int ni = 0; ni < 4; ni++)
#pragma unroll
            for (int k = 0; k < 4; k++) acc[mi][ni][k] = 0.f;

    // ---- prefetch helpers ----
    auto prefetch = [&](int tile, int buf) {
        int jc = jbase + tile * 128;
        // adj: 128 rows x 128 ints, dst stride SAS
#pragma unroll
        for (int u = 0; u < 16; u++) {
            int idx = u * 256 + t;
            int r = idx >> 5, c4 = idx & 31;
            cpasync16(smbase + (uint32_t)(SADJ_OFF + r * SAS + c4 * 4) * 4u,
                      adj + (size_t)(i0 + r) * NN + jc + c4 * 4);
        }
        // B hi/lo: 64 rows x 64 u32 each, dst stride SPS
        uint32_t bofs = (uint32_t)(SB_OFF + buf * 8704);
#pragma unroll
        for (int u = 0; u < 4; u++) {
            int idx = u * 256 + t;
            int f = idx >> 4, c4 = idx & 15;
            cpasync16(smbase + (bofs + (uint32_t)(f * SPS + c4 * 4)) * 4u,
                      (const char*)(g_HThi + (size_t)f * NN + jc) + c4 * 16);
        }
#pragma unroll
        for (int u = 0; u < 4; u++) {
            int idx = u * 256 + t;
            int f = idx >> 4, c4 = idx & 15;
            cpasync16(smbase + (bofs + 4352u + (uint32_t)(f * SPS + c4 * 4)) * 4u,
                      (const char*)(g_HTlo + (size_t)f * NN + jc) + c4 * 16);
        }
        cp_commit();
    };

    // prologue: prefetch tile 0 into buffer 0
    prefetch(0, 0);
    cp_wait0();
    __syncthreads();

    for (int tt = 0; tt < 32; tt++) {
        int b = tt & 1;
        int jc = jbase + tt * 128;

        // --- build P tile from smem adj + colf ---
        {
            const float4* colf = g_colf + jc + half * 64;
#pragma unroll 4
            for (int u = 0; u < 16; u++) {
                int4 av = adjS[u];
                int l = u * 4;
                float4 c0 = colf[l + 0], c1 = colf[l + 1], c2v = colf[l + 2], c3 = colf[l + 3];
                float p0 = (av.x > 0) ? ((c0.z >= nsi) ? Gi * c0.x : c0.y) : 0.f;
                float p1 = (av.y > 0) ? ((c1.z >= nsi) ? Gi * c1.x : c1.y) : 0.f;
                float p2 = (av.z > 0) ? ((c2v.z >= nsi) ? Gi * c2v.x : c2v.y) : 0.f;
                float p3 = (av.w > 0) ? ((c3.z >= nsi) ? Gi * c3.x : c3.y) : 0.f;
                rsum += (p0 + p1) + (p2 + p3);
                uint32_t h01, h23, l01, l23;
                asm("cvt.rn.bf16x2.f32 %0, %1, %2;" : "=r"(h01) : "f"(p1), "f"(p0));
                asm("cvt.rn.bf16x2.f32 %0, %1, %2;" : "=r"(h23) : "f"(p3), "f"(p2));
                float q0 = p0 - __uint_as_float(h01 << 16);
                float q1 = p1 - __uint_as_float(h01 & 0xffff0000u);
                float q2 = p2 - __uint_as_float(h23 << 16);
                float q3 = p3 - __uint_as_float(h23 & 0xffff0000u);
                asm("cvt.rn.bf16x2.f32 %0, %1, %2;" : "=r"(l01) : "f"(q1), "f"(q0));
                asm("cvt.rn.bf16x2.f32 %0, %1, %2;" : "=r"(l23) : "f"(q3), "f"(q2));
                pDhi[u] = (uint64_t)h01 | ((uint64_t)h23 << 32);
                pDlo[u] = (uint64_t)l01 | ((uint64_t)l23 << 32);
            }
        }
        __syncthreads();  // P visible; sAdj fully consumed

        // --- prefetch next tile (adj -> sAdj, B -> buffer b^1) ---
        if (tt + 1 < 32) prefetch(tt + 1, b ^ 1);
        else cp_commit();  // keep wait_group balanced

        // --- MMA over k=128, 3-pass hi/lo, fragments via ldmatrix.x4 ---
        uint32_t bBhi = bB_l + (uint32_t)(b * 8704) * 4u;
        uint32_t bBlo = bBhi + 4352u * 4u;
#pragma unroll
        for (int kk = 0; kk < 8; kk++) {
            uint32_t kb = (uint32_t)kk * 32u;
            uint32_t AH0[4], AH1[4], AL0[4], AL1[4], BH0[4], BH1[4], BL0[4], BL1[4];
            ldsm4(AH0, aPhi + kb);
            ldsm4(AH1, aPhi + mstep + kb);
            ldsm4(BH0, bBhi + kb);
            ldsm4(BH1, bBhi + nstep + kb);
            ldsm4(AL0, aPlo + kb);
            ldsm4(AL1, aPlo + mstep + kb);
            ldsm4(BL0, bBlo + kb);
            ldsm4(BL1, bBlo + nstep + kb);
            // hi * hi
            mma_bf16(acc[0][0], AH0, BH0[0], BH0[1]);
            mma_bf16(acc[0][1], AH0, BH0[2], BH0[3]);
            mma_bf16(acc[0][2], AH0, BH1[0], BH1[1]);
            mma_bf16(acc[0][3], AH0, BH1[2], BH1[3]);
            mma_bf16(acc[1][0], AH1, BH0[0], BH0[1]);
            mma_bf16(acc[1][1], AH1, BH0[2], BH0[3]);
            mma_bf16(acc[1][2], AH1, BH1[0], BH1[1]);
            mma_bf16(acc[1][3], AH1, BH1[2], BH1[3]);
            // hi * lo
            mma_bf16(acc[0][0], AH0, BL0[0], BL0[1]);
            mma_bf16(acc[0][1], AH0, BL0[2], BL0[3]);
            mma_bf16(acc[0][2], AH0, BL1[0], BL1[1]);
            mma_bf16(acc[0][3], AH0, BL1[2], BL1[3]);
            mma_bf16(acc[1][0], AH1, BL0[0], BL0[1]);
            mma_bf16(acc[1][1], AH1, BL0[2], BL0[3]);
            mma_bf16(acc[1][2], AH1, BL1[0], BL1[1]);
            mma_bf16(acc[1][3], AH1, BL1[2], BL1[3]);
            // lo * hi
            mma_bf16(acc[0][0], AL0, BH0[0], BH0[1]);
            mma_bf16(acc[0][1], AL0, BH0[2], BH0[3]);
            mma_bf16(acc[0][2], AL0, BH1[0], BH1[1]);
            mma_bf16(acc[0][3], AL0, BH1[2], BH1[3]);
            mma_bf16(acc[1][0], AL1, BH0[0], BH0[1]);
            mma_bf16(acc[1][1], AL1, BH0[2], BH0[3]);
            mma_bf16(acc[1][2], AL1, BH1[0], BH1[1]);
            mma_bf16(acc[1][3], AL1, BH1[2], BH1[3]);
        }
        cp_wait0();
        __syncthreads();
    }

    // ---- row sums ----
    {
        float o = __shfl_xor_sync(0xffffffffu, rsum, 1);
        if (half == 0) g_psum[(size_t)jh * NN + i0 + row] = rsum + o;
    }

    // ---- store partial numerators ----
#pragma unroll
    for (int mi = 0; mi < 2; mi++) {
        int r0 = i0 + wr * 32 + mi * 16 + g;
#pragma unroll
        for (int ni = 0; ni < 4; ni++) {
            int c = wc * 32 + ni * 8 + tg * 2;
            *(float2*)(g_part + ((size_t)jh * NN + r0) * FOUT + c) =
                make_float2(acc[mi][ni][0], acc[mi][ni][1]);
            *(float2*)(g_part + ((size_t)jh * NN + r0 + 8) * FOUT + c) =
                make_float2(acc[mi][ni][2], acc[mi][ni][3]);
        }
    }
}

// ---------------- Kernel C: combine halves + normalize + ELU ----------------
__global__ __launch_bounds__(256) void k_combine(float* __restrict__ out) {
    int v = blockIdx.x * blockDim.x + threadIdx.x;  // float4 index
    int row = v >> 4;
    float s = g_psum[row] + g_psum[NN + row];
    float inv = 1.0f / s;
    float4 a0 = ((const float4*)g_part)[v];
    float4 a1 = ((const float4*)(g_part + (size_t)NN * FOUT))[v];
    float4 o;
    o.x = (a0.x + a1.x) * inv;
    o.y = (a0.y + a1.y) * inv;
    o.z = (a0.z + a1.z) * inv;
    o.w = (a0.w + a1.w) * inv;
    o.x = (o.x > 0.f) ? o.x : expm1f(o.x);
    o.y = (o.y > 0.f) ? o.y : expm1f(o.y);
    o.z = (o.z > 0.f) ? o.z : expm1f(o.z);
    o.w = (o.w > 0.f) ? o.w : expm1f(o.w);
    ((float4*)out)[v] = o;
}

extern "C" void kernel_launch(void* const* d_in, const int* in_sizes, int n_in,
                              void* d_out, int out_size) {
    const float* X = (const float*)d_in[0];   // 8192x512
    const int* adj = (const int*)d_in[1];     // 8192x8192
    const float* W = (const float*)d_in[2];   // 512x64
    const float* a = (const float*)d_in[3];   // 128x1
    float* out = (float*)d_out;               // 8192x64

    float* H;
    cudaGetSymbolAddress((void**)&H, g_h);

    static int inited = 0;
    if (!inited) {
        cudaFuncSetAttribute(k_attn, cudaFuncAttributeMaxDynamicSharedMemorySize,
                             SMEM_U32 * 4);
        inited = 1;
    }

    k_gemm_h<<<NN / 64, 256>>>(X, W, H);
    k_scores<<<NN / 256, 256>>>(H, a);
    k_transpose<<<NN / 64, 256>>>();
    k_attn<<<128, 256, SMEM_U32 * 4>>>(adj);
    k_combine<<<(NN * FOUT / 4) / 256, 256>>>(out);
}

// round 12
// speedup vs baseline: 1.4972x; 1.4972x over previous
#include <cuda_runtime.h>
#include <cuda_bf16.h>
#include <cstdint>

#define NN 8192
#define FIN 512
#define FOUT 64

// ---------------- scratch globals (no allocations allowed) ----------------
__device__ float g_h[NN * FOUT];
__device__ float g_ssrc[NN];
__device__ float g_G[NN];                    // exp(0.8 * s_src)
__device__ float4 g_colf[NN];                // {F=exp(sd), F02=exp(0.2 sd), sd, 0}
__device__ __nv_bfloat16 g_HThi[FOUT * NN];  // H^T high bf16, [f][i]
__device__ __nv_bfloat16 g_HTlo[FOUT * NN];  // H^T residual bf16
__device__ float g_part[2 * NN * FOUT];      // partial numerators per j-half
__device__ float g_psum[2 * NN];             // partial row sums per j-half

__device__ __forceinline__ uint32_t smem_u32(const void* p) {
    uint32_t a;
    asm("{ .reg .u64 t; cvta.to.shared.u64 t, %1; cvt.u32.u64 %0, t; }" : "=r"(a) : "l"(p));
    return a;
}
__device__ __forceinline__ void ldsm4(uint32_t* r, uint32_t addr) {
    asm volatile("ldmatrix.sync.aligned.m8n8.x4.shared.b16 {%0,%1,%2,%3}, [%4];"
                 : "=r"(r[0]), "=r"(r[1]), "=r"(r[2]), "=r"(r[3]) : "r"(addr));
}
__device__ __forceinline__ void mma_bf16(float* c, const uint32_t* a, uint32_t b0, uint32_t b1) {
    asm volatile(
        "mma.sync.aligned.m16n8k16.row.col.f32.bf16.bf16.f32 "
        "{%0,%1,%2,%3}, {%4,%5,%6,%7}, {%8,%9}, {%0,%1,%2,%3};"
        : "+f"(c[0]), "+f"(c[1]), "+f"(c[2]), "+f"(c[3])
        : "r"(a[0]), "r"(a[1]), "r"(a[2]), "r"(a[3]), "r"(b0), "r"(b1));
}
__device__ __forceinline__ void mbar_init(uint32_t a, uint32_t c) {
    asm volatile("mbarrier.init.shared.b64 [%0], %1;" :: "r"(a), "r"(c) : "memory");
}
__device__ __forceinline__ void mbar_expect(uint32_t a, uint32_t tx) {
    asm volatile("mbarrier.arrive.expect_tx.shared.b64 _, [%0], %1;" :: "r"(a), "r"(tx) : "memory");
}
__device__ __forceinline__ void mbar_wait(uint32_t a, uint32_t par) {
    asm volatile(
        "{\n\t.reg .pred P1;\n\t"
        "WL_%=:\n\t"
        "mbarrier.try_wait.parity.acquire.cta.shared::cta.b64 P1, [%0], %1, 0x989680;\n\t"
        "@P1 bra.uni WD_%=;\n\t"
        "bra.uni WL_%=;\n\t"
        "WD_%=:\n\t}"
        :: "r"(a), "r"(par) : "memory");
}
__device__ __forceinline__ void bulk_g2s(uint32_t dst, const void* src, uint32_t bytes, uint32_t mbar) {
    asm volatile(
        "cp.async.bulk.shared::cta.global.mbarrier::complete_tx::bytes [%0], [%1], %2, [%3];"
        :: "r"(dst), "l"(src), "r"(bytes), "r"(mbar) : "memory");
}

// ---------------- Kernel A: h = X @ W ----------------
__global__ __launch_bounds__(256) void k_gemm_h(const float* __restrict__ X,
                                                const float* __restrict__ W,
                                                float* __restrict__ H) {
    __shared__ float sA[32][65];
    __shared__ float sB[32][68];
    int t = threadIdx.x;
    int m0 = blockIdx.x * 64;
    int tr = t >> 4, tc = t & 15;
    float acc[4][4];
#pragma unroll
    for (int i = 0; i < 4; i++)
#pragma unroll
        for (int j = 0; j < 4; j++) acc[i][j] = 0.f;

    float rA[8], rB[8];
#pragma unroll
    for (int u = 0; u < 8; u++) {
        int g = u * 256 + t;
        int m = g >> 5, k = g & 31;
        rA[u] = X[(m0 + m) * FIN + k];
    }
#pragma unroll
    for (int u = 0; u < 8; u++) {
        int g = u * 256 + t;
        int k = g >> 6, n = g & 63;
        rB[u] = W[k * FOUT + n];
    }

    for (int kc = 0; kc < 16; kc++) {
        __syncthreads();
#pragma unroll
        for (int u = 0; u < 8; u++) {
            int g = u * 256 + t;
            int m = g >> 5, k = g & 31;
            sA[k][m] = rA[u];
        }
#pragma unroll
        for (int u = 0; u < 8; u++) {
            int g = u * 256 + t;
            int k = g >> 6, n = g & 63;
            sB[k][n] = rB[u];
        }
        __syncthreads();
        if (kc + 1 < 16) {
            int k0 = (kc + 1) * 32;
#pragma unroll
            for (int u = 0; u < 8; u++) {
                int g = u * 256 + t;
                int m = g >> 5, k = g & 31;
                rA[u] = X[(m0 + m) * FIN + k0 + k];
            }
#pragma unroll
            for (int u = 0; u < 8; u++) {
                int g = u * 256 + t;
                int k = g >> 6, n = g & 63;
                rB[u] = W[(k0 + k) * FOUT + n];
            }
        }
#pragma unroll
        for (int k = 0; k < 32; k++) {
            float a[4], b[4];
#pragma unroll
            for (int i = 0; i < 4; i++) a[i] = sA[k][tr + 16 * i];
#pragma unroll
            for (int j = 0; j < 4; j++) b[j] = sB[k][tc + 16 * j];
#pragma unroll
            for (int i = 0; i < 4; i++)
#pragma unroll
                for (int j = 0; j < 4; j++) acc[i][j] += a[i] * b[j];
        }
    }
#pragma unroll
    for (int i = 0; i < 4; i++)
#pragma unroll
        for (int j = 0; j < 4; j++)
            H[(m0 + tr + 16 * i) * FOUT + tc + 16 * j] = acc[i][j];
}

// ---------------- Kernel A2: scores + exp factors ----------------
__global__ __launch_bounds__(256) void k_scores(const float* __restrict__ H,
                                                const float* __restrict__ a) {
    int i = blockIdx.x * blockDim.x + threadIdx.x;
    const float4* hr = (const float4*)(H + i * FOUT);
    const float4* av = (const float4*)a;
    float ss = 0.f, sd = 0.f;
#pragma unroll
    for (int f = 0; f < 16; f++) {
        float4 h = hr[f];
        float4 as = av[f];
        float4 ad = av[16 + f];
        ss += h.x * as.x + h.y * as.y + h.z * as.z + h.w * as.w;
        sd += h.x * ad.x + h.y * ad.y + h.z * ad.z + h.w * ad.w;
    }
    g_ssrc[i] = ss;
    g_G[i] = expf(0.8f * ss);
    g_colf[i] = make_float4(expf(sd), expf(0.2f * sd), sd, 0.f);
}

// ---------------- Kernel A3: transpose H -> HT hi/lo bf16 ----------------
__global__ __launch_bounds__(256) void k_transpose() {
    __shared__ float tile[64][65];
    int t = threadIdx.x;
    int i0 = blockIdx.x * 64;
#pragma unroll
    for (int u = 0; u < 16; u++) {
        int idx = u * 256 + t;
        int r = idx >> 6, c = idx & 63;
        tile[r][c] = g_h[(i0 + r) * FOUT + c];
    }
    __syncthreads();
#pragma unroll
    for (int u = 0; u < 16; u++) {
        int idx = u * 256 + t;
        int f = idx >> 6, i = idx & 63;
        float v = tile[i][f];
        __nv_bfloat16 hb = __float2bfloat16(v);
        float hv = __bfloat162float(hb);
        __nv_bfloat16 lb = __float2bfloat16(v - hv);
        g_HThi[f * NN + i0 + i] = hb;
        g_HTlo[f * NN + i0 + i] = lb;
    }
}

// ---------------- Kernel B: HMMA attention, bulk-copy pipelined ----------------
// smem (u32 offsets):
//   sPhi   [128][68]                 at 0       (8704)
//   sPlo   [128][68]                 at 8704    (8704)
//   sB     2 x {hi 4352, lo 4352}    at 17408   (17408)
//   sAdj   [128][132]                at 34816   (16896)
//   sColf  float4[128]               at 51712   (512)
//   mbars  3 x 8B                    at 52224   (6)
#define SPS 68
#define SAS 132
#define SB_OFF 17408
#define SADJ_OFF 34816
#define SCOLF_OFF 51712
#define SMB_OFF 52224
#define SMEM_U32 52232  // 208928 bytes

#define ADJ_TX (128u * 512u + 2048u)
#define B_TX (128u * 256u)

__global__ __launch_bounds__(256, 1) void k_attn(const int* __restrict__ adj) {
    extern __shared__ uint32_t sm[];
    uint32_t* sPhi = sm;
    uint32_t* sPlo = sm + 8704;
    uint32_t* sAdj = sm + SADJ_OFF;
    uint32_t smbase = smem_u32(sm);
    uint32_t mbA = smbase + SMB_OFF * 4u;
    uint32_t mbB0 = mbA + 8u;
    uint32_t mbB1 = mbA + 16u;

    int t = threadIdx.x;
    int w = t >> 5, lane = t & 31;
    int g = lane >> 2, tg = lane & 3;
    int rb = (int)blockIdx.x >> 1, jh = (int)blockIdx.x & 1;
    int i0 = rb * 128, jbase = jh * 4096;

    if (t == 0) {
        mbar_init(mbA, 1);
        mbar_init(mbB0, 1);
        mbar_init(mbB1, 1);
    }
    __syncthreads();

    // ---- prefetch issuer (each thread issues <=1-2 bulk ops) ----
    auto issue_prefetch = [&](int jc, int buf) {
        if (t < 128) {
            if (t == 0) {
                mbar_expect(mbA, ADJ_TX);
                bulk_g2s(smbase + (uint32_t)SCOLF_OFF * 4u, g_colf + jc, 2048u, mbA);
            }
            bulk_g2s(smbase + (uint32_t)(SADJ_OFF + t * SAS) * 4u,
                     adj + (size_t)(i0 + t) * NN + jc, 512u, mbA);
        } else if (t < 192) {
            uint32_t mb = buf ? mbB1 : mbB0;
            if (t == 128) mbar_expect(mb, B_TX);
            int f = t - 128;
            bulk_g2s(smbase + (uint32_t)(SB_OFF + buf * 8704 + f * SPS) * 4u,
                     g_HThi + (size_t)f * NN + jc, 256u, mb);
        } else {
            uint32_t mb = buf ? mbB1 : mbB0;
            int f = t - 192;
            bulk_g2s(smbase + (uint32_t)(SB_OFF + buf * 8704 + 4352 + f * SPS) * 4u,
                     g_HTlo + (size_t)f * NN + jc, 256u, mb);
        }
    };

    // ---- P-build mapping: thread -> (row, half of 64 cols) ----
    int row = t >> 1;
    int half = t & 1;
    float si = g_ssrc[i0 + row];
    float Gi = g_G[i0 + row];
    float nsi = -si;
    float rsum = 0.f;
    uint64_t* pDhi = (uint64_t*)sPhi + (size_t)row * (SPS / 2) + half * 16;
    uint64_t* pDlo = (uint64_t*)sPlo + (size_t)row * (SPS / 2) + half * 16;
    const int4* adjS = (const int4*)(sAdj + row * SAS + half * 64);
    const float4* colfS = (const float4*)(sm + SCOLF_OFF) + half * 64;

    // ---- MMA mapping: 8 warps = 4(wr) x 2(wc), warp tile 32m x 32n ----
    int wr = w >> 1, wc = w & 1;
    int a_r = ((lane >> 3) & 1) * 8 + (lane & 7);
    uint32_t a_cb = (uint32_t)(lane >> 4) * 16u;
    int b_r = (lane >> 4) * 8 + (lane & 7);
    uint32_t b_cb = (uint32_t)((lane >> 3) & 1) * 16u;

    uint32_t aPhi = smbase + (uint32_t)((wr * 32 + a_r) * SPS) * 4u + a_cb;
    uint32_t aPlo = aPhi + 8704u * 4u;
    uint32_t bB_l = smbase + SB_OFF * 4u + (uint32_t)((wc * 32 + b_r) * SPS) * 4u + b_cb;
    const uint32_t mstep = 16u * SPS * 4u;
    const uint32_t nstep = 16u * SPS * 4u;

    float acc[2][4][4];
#pragma unroll
    for (int mi = 0; mi < 2; mi++)
#pragma unroll
        for (int ni = 0; ni < 4; ni++)
#pragma unroll
            for (int k = 0; k < 4; k++) acc[mi][ni][k] = 0.f;

    // prologue: prefetch tile 0 (adj+colf -> single buf; B -> buf 0)
    issue_prefetch(jbase, 0);

    int parA = 0;
    int parB[2] = {0, 0};

    for (int tt = 0; tt < 32; tt++) {
        int b = tt & 1;

        // --- wait adj/colf tile tt ---
        mbar_wait(mbA, parA);
        parA ^= 1;

        // --- build P tile from smem adj + smem colf ---
#pragma unroll 4
        for (int u = 0; u < 16; u++) {
            int4 av = adjS[u];
            int l = u * 4;
            float4 c0 = colfS[l + 0], c1 = colfS[l + 1], c2v = colfS[l + 2], c3 = colfS[l + 3];
            float p0 = (av.x > 0) ? ((c0.z >= nsi) ? Gi * c0.x : c0.y) : 0.f;
            float p1 = (av.y > 0) ? ((c1.z >= nsi) ? Gi * c1.x : c1.y) : 0.f;
            float p2 = (av.z > 0) ? ((c2v.z >= nsi) ? Gi * c2v.x : c2v.y) : 0.f;
            float p3 = (av.w > 0) ? ((c3.z >= nsi) ? Gi * c3.x : c3.y) : 0.f;
            rsum += (p0 + p1) + (p2 + p3);
            uint32_t h01, h23, l01, l23;
            asm("cvt.rn.bf16x2.f32 %0, %1, %2;" : "=r"(h01) : "f"(p1), "f"(p0));
            asm("cvt.rn.bf16x2.f32 %0, %1, %2;" : "=r"(h23) : "f"(p3), "f"(p2));
            float q0 = p0 - __uint_as_float(h01 << 16);
            float q1 = p1 - __uint_as_float(h01 & 0xffff0000u);
            float q2 = p2 - __uint_as_float(h23 << 16);
            float q3 = p3 - __uint_as_float(h23 & 0xffff0000u);
            asm("cvt.rn.bf16x2.f32 %0, %1, %2;" : "=r"(l01) : "f"(q1), "f"(q0));
            asm("cvt.rn.bf16x2.f32 %0, %1, %2;" : "=r"(l23) : "f"(q3), "f"(q2));
            pDhi[u] = (uint64_t)h01 | ((uint64_t)h23 << 32);
            pDlo[u] = (uint64_t)l01 | ((uint64_t)l23 << 32);
        }
        __syncthreads();  // P visible to all warps; adj+colf fully consumed

        // --- prefetch tile tt+1 (adj/colf reuse buffer; B -> buf b^1) ---
        if (tt + 1 < 32) issue_prefetch(jbase + (tt + 1) * 128, b ^ 1);

        // --- wait B tile tt, then MMA (3-pass hi/lo via ldmatrix.x4) ---
        mbar_wait(b ? mbB1 : mbB0, parB[b]);
        parB[b] ^= 1;

        uint32_t bBhi = bB_l + (uint32_t)(b * 8704) * 4u;
        uint32_t bBlo = bBhi + 4352u * 4u;
#pragma unroll
        for (int kk = 0; kk < 8; kk++) {
            uint32_t kb = (uint32_t)kk * 32u;
            uint32_t AH0[4], AH1[4], AL0[4], AL1[4], BH0[4], BH1[4], BL0[4], BL1[4];
            ldsm4(AH0, aPhi + kb);
            ldsm4(AH1, aPhi + mstep + kb);
            ldsm4(BH0, bBhi + kb);
            ldsm4(BH1, bBhi + nstep + kb);
            ldsm4(AL0, aPlo + kb);
            ldsm4(AL1, aPlo + mstep + kb);
            ldsm4(BL0, bBlo + kb);
            ldsm4(BL1, bBlo + nstep + kb);
            // hi * hi
            mma_bf16(acc[0][0], AH0, BH0[0], BH0[1]);
            mma_bf16(acc[0][1], AH0, BH0[2], BH0[3]);
            mma_bf16(acc[0][2], AH0, BH1[0], BH1[1]);
            mma_bf16(acc[0][3], AH0, BH1[2], BH1[3]);
            mma_bf16(acc[1][0], AH1, BH0[0], BH0[1]);
            mma_bf16(acc[1][1], AH1, BH0[2], BH0[3]);
            mma_bf16(acc[1][2], AH1, BH1[0], BH1[1]);
            mma_bf16(acc[1][3], AH1, BH1[2], BH1[3]);
            // hi * lo
            mma_bf16(acc[0][0], AH0, BL0[0], BL0[1]);
            mma_bf16(acc[0][1], AH0, BL0[2], BL0[3]);
            mma_bf16(acc[0][2], AH0, BL1[0], BL1[1]);
            mma_bf16(acc[0][3], AH0, BL1[2], BL1[3]);
            mma_bf16(acc[1][0], AH1, BL0[0], BL0[1]);
            mma_bf16(acc[1][1], AH1, BL0[2], BL0[3]);
            mma_bf16(acc[1][2], AH1, BL1[0], BL1[1]);
            mma_bf16(acc[1][3], AH1, BL1[2], BL1[3]);
            // lo * hi
            mma_bf16(acc[0][0], AL0, BH0[0], BH0[1]);
            mma_bf16(acc[0][1], AL0, BH0[2], BH0[3]);
            mma_bf16(acc[0][2], AL0, BH1[0], BH1[1]);
            mma_bf16(acc[0][3], AL0, BH1[2], BH1[3]);
            mma_bf16(acc[1][0], AL1, BH0[0], BH0[1]);
            mma_bf16(acc[1][1], AL1, BH0[2], BH0[3]);
            mma_bf16(acc[1][2], AL1, BH1[0], BH1[1]);
            mma_bf16(acc[1][3], AL1, BH1[2], BH1[3]);
        }
        __syncthreads();  // MMA reads done before next P-build overwrites sP
    }

    // ---- row sums ----
    {
        float o = __shfl_xor_sync(0xffffffffu, rsum, 1);
        if (half == 0) g_psum[(size_t)jh * NN + i0 + row] = rsum + o;
    }

    // ---- store partial numerators ----
#pragma unroll
    for (int mi = 0; mi < 2; mi++) {
        int r0 = i0 + wr * 32 + mi * 16 + g;
#pragma unroll
        for (int ni = 0; ni < 4; ni++) {
            int c = wc * 32 + ni * 8 + tg * 2;
            *(float2*)(g_part + ((size_t)jh * NN + r0) * FOUT + c) =
                make_float2(acc[mi][ni][0], acc[mi][ni][1]);
            *(float2*)(g_part + ((size_t)jh * NN + r0 + 8) * FOUT + c) =
                make_float2(acc[mi][ni][2], acc[mi][ni][3]);
        }
    }
}

// ---------------- Kernel C: combine halves + normalize + ELU ----------------
__global__ __launch_bounds__(256) void k_combine(float* __restrict__ out) {
    int v = blockIdx.x * blockDim.x + threadIdx.x;  // float4 index
    int row = v >> 4;
    float s = g_psum[row] + g_psum[NN + row];
    float inv = 1.0f / s;
    float4 a0 = ((const float4*)g_part)[v];
    float4 a1 = ((const float4*)(g_part + (size_t)NN * FOUT))[v];
    float4 o;
    o.x = (a0.x + a1.x) * inv;
    o.y = (a0.y + a1.y) * inv;
    o.z = (a0.z + a1.z) * inv;
    o.w = (a0.w + a1.w) * inv;
    o.x = (o.x > 0.f) ? o.x : expm1f(o.x);
    o.y = (o.y > 0.f) ? o.y : expm1f(o.y);
    o.z = (o.z > 0.f) ? o.z : expm1f(o.z);
    o.w = (o.w > 0.f) ? o.w : expm1f(o.w);
    ((float4*)out)[v] = o;
}

extern "C" void kernel_launch(void* const* d_in, const int* in_sizes, int n_in,
                              void* d_out, int out_size) {
    const float* X = (const float*)d_in[0];   // 8192x512
    const int* adj = (const int*)d_in[1];     // 8192x8192
    const float* W = (const float*)d_in[2];   // 512x64
    const float* a = (const float*)d_in[3];   // 128x1
    float* out = (float*)d_out;               // 8192x64

    float* H;
    cudaGetSymbolAddress((void**)&H, g_h);

    static int inited = 0;
    if (!inited) {
        cudaFuncSetAttribute(k_attn, cudaFuncAttributeMaxDynamicSharedMemorySize,
                             SMEM_U32 * 4);
        inited = 1;
    }

    k_gemm_h<<<NN / 64, 256>>>(X, W, H);
    k_scores<<<NN / 256, 256>>>(H, a);
    k_transpose<<<NN / 64, 256>>>();
    k_attn<<<128, 256, SMEM_U32 * 4>>>(adj);
    k_combine<<<(NN * FOUT / 4) / 256, 256>>>(out);
}